// round 3
// baseline (speedup 1.0000x reference)
#include <cuda_runtime.h>
#include <math.h>
#include <stdint.h>
#include <stddef.h>

#define BB 2
#define NN 2048
#define EE 256
#define HH 4
#define DKK 64
#define MTOT (BB*NN)

#define TQ 64
#define TK 64

// Scratch (no allocations allowed in kernel_launch)
__device__ float g_Q[BB*HH*NN*DKK];   // 4 MB, layout [b][h][n][dk], pre-scaled by 1/sqrt(dk)
__device__ float g_K[BB*HH*NN*DKK];
__device__ float g_V[BB*HH*NN*DKK];
__device__ float g_C[BB*NN*EE];       // concat heads [b][n][h*dk+e]
__device__ float g_WoT[EE*EE];        // Wo transposed: WoT[d][o] = Wo[o][d]

// ---------------------------------------------------------------------------
// Kernel A: fused Q/K/V projection. Block = 8 rows of X, 256 threads.
// Thread t owns (h = t/64, e = t%64) and computes q,k,v for all 8 rows,
// so each weight element is loaded once per 8 rows (L2-resident weights).
// ---------------------------------------------------------------------------
__global__ void __launch_bounds__(256) qkv_kernel(
    const float* __restrict__ X, const float* __restrict__ Wq,
    const float* __restrict__ Wk, const float* __restrict__ Wv)
{
    __shared__ float xs[8][EE];
    const int m0 = blockIdx.x * 8;
    const int t  = threadIdx.x;

    for (int i = t * 4; i < 8 * EE; i += 256 * 4) {
        int r = i >> 8, d = i & 255;
        *(float4*)&xs[r][d] = *(const float4*)&X[(size_t)(m0 + r) * EE + d];
    }
    __syncthreads();

    const int h = t >> 6, e = t & 63;
    const float* wq = Wq + (size_t)h * EE * DKK + e;
    const float* wk = Wk + (size_t)h * EE * DKK + e;
    const float* wv = Wv + (size_t)h * EE * DKK + e;

    float aq[8], ak[8], av[8];
    #pragma unroll
    for (int r = 0; r < 8; r++) { aq[r] = 0.f; ak[r] = 0.f; av[r] = 0.f; }

    #pragma unroll 2
    for (int d = 0; d < EE; d++) {
        float q_ = wq[d * DKK];
        float k_ = wk[d * DKK];
        float v_ = wv[d * DKK];
        #pragma unroll
        for (int r = 0; r < 8; r++) {
            float x_ = xs[r][d];
            aq[r] = fmaf(x_, q_, aq[r]);
            ak[r] = fmaf(x_, k_, ak[r]);
            av[r] = fmaf(x_, v_, av[r]);
        }
    }

    #pragma unroll
    for (int r = 0; r < 8; r++) {
        int m = m0 + r;
        int b = m / NN, n = m % NN;
        size_t base = ((size_t)(b * HH + h) * NN + n) * DKK + e;
        g_Q[base] = aq[r] * 0.125f;   // 1/sqrt(64) folded into Q
        g_K[base] = ak[r];
        g_V[base] = av[r];
    }
}

// ---------------------------------------------------------------------------
// Kernel B: flash attention. Grid = (N/TQ, B*H). Block = 256 threads as
// 16(tx) x 16(ty), each thread a 4x4 micro-tile.
// Smem = Qs[64][64] + KP[64][64] + Vs[64][64] = 48 KB exactly.
// KP holds the K tile during S=QK^T (XOR-swizzled columns: (d+kc)&63 so the
// kc-strided reads are bank-conflict-free), then is overwritten with the P
// tile (same swizzle) for the PV GEMM.
// Mask uses -1e30 (never -inf) so max/exp algebra is NaN-free; a fully
// masked tile contributes garbage that the next rescale (alpha=0) wipes out.
// ---------------------------------------------------------------------------
__global__ void __launch_bounds__(256) attn_kernel(const int* __restrict__ Adj)
{
    __shared__ float Qs[TQ][DKK];
    __shared__ float KP[TK][DKK];
    __shared__ float Vs[TK][DKK];

    const int t  = threadIdx.x;
    const int tx = t & 15, ty = t >> 4;
    const int q0 = blockIdx.x * TQ;
    const int bh = blockIdx.y;
    const int b  = bh >> 2;   // H = 4
    const int h  = bh & 3;

    const float* Qg = g_Q + ((size_t)bh * NN + q0) * DKK;
    for (int i = t * 4; i < TQ * DKK; i += 256 * 4) {
        int r = i >> 6, d = i & 63;
        *(float4*)&Qs[r][d] = *(const float4*)&Qg[(size_t)r * DKK + d];
    }

    float m_[4], l_[4], oacc[4][4];
    #pragma unroll
    for (int i = 0; i < 4; i++) {
        m_[i] = -1e30f; l_[i] = 0.f;
        #pragma unroll
        for (int j = 0; j < 4; j++) oacc[i][j] = 0.f;
    }

    const int* Arow = Adj + ((size_t)(b * NN) + q0 + ty * 4) * NN;
    __syncthreads();   // Qs ready

    for (int k0 = 0; k0 < NN; k0 += TK) {
        // ---- load K (swizzled) and V tiles ----
        const float* Kg = g_K + ((size_t)bh * NN + k0) * DKK;
        const float* Vg = g_V + ((size_t)bh * NN + k0) * DKK;
        for (int i = t * 4; i < TK * DKK; i += 256 * 4) {
            int kc = i >> 6, d0 = i & 63;
            float4 kv = *(const float4*)&Kg[(size_t)kc * DKK + d0];
            KP[kc][(d0 + 0 + kc) & 63] = kv.x;
            KP[kc][(d0 + 1 + kc) & 63] = kv.y;
            KP[kc][(d0 + 2 + kc) & 63] = kv.z;
            KP[kc][(d0 + 3 + kc) & 63] = kv.w;
            *(float4*)&Vs[kc][d0] = *(const float4*)&Vg[(size_t)kc * DKK + d0];
        }
        __syncthreads();

        // ---- S = Q K^T (scale already folded into Q) ----
        float s_[4][4];
        #pragma unroll
        for (int i = 0; i < 4; i++)
            #pragma unroll
            for (int j = 0; j < 4; j++) s_[i][j] = 0.f;

        #pragma unroll 4
        for (int d = 0; d < DKK; d++) {
            float rq[4], rk[4];
            #pragma unroll
            for (int i = 0; i < 4; i++) rq[i] = Qs[ty * 4 + i][d];
            #pragma unroll
            for (int j = 0; j < 4; j++) {
                int kc = tx * 4 + j;
                rk[j] = KP[kc][(d + kc) & 63];
            }
            #pragma unroll
            for (int i = 0; i < 4; i++)
                #pragma unroll
                for (int j = 0; j < 4; j++)
                    s_[i][j] = fmaf(rq[i], rk[j], s_[i][j]);
        }

        // ---- adjacency mask (direct gmem int4, L2-resident, H-fold reuse) ----
        #pragma unroll
        for (int i = 0; i < 4; i++) {
            const int4 am = *(const int4*)&Arow[(size_t)i * NN + k0 + tx * 4];
            if (am.x <= 0) s_[i][0] = -1e30f;
            if (am.y <= 0) s_[i][1] = -1e30f;
            if (am.z <= 0) s_[i][2] = -1e30f;
            if (am.w <= 0) s_[i][3] = -1e30f;
        }

        __syncthreads();   // all done reading K from KP; about to overwrite with P

        // ---- online softmax update, write P (swizzled) into KP ----
        #pragma unroll
        for (int i = 0; i < 4; i++) {
            float mx = fmaxf(fmaxf(s_[i][0], s_[i][1]), fmaxf(s_[i][2], s_[i][3]));
            mx = fmaxf(mx, __shfl_xor_sync(0xffffffffu, mx, 8, 16));
            mx = fmaxf(mx, __shfl_xor_sync(0xffffffffu, mx, 4, 16));
            mx = fmaxf(mx, __shfl_xor_sync(0xffffffffu, mx, 2, 16));
            mx = fmaxf(mx, __shfl_xor_sync(0xffffffffu, mx, 1, 16));
            float mn = fmaxf(m_[i], mx);
            float alpha = expf(m_[i] - mn);
            float rs = 0.f;
            #pragma unroll
            for (int j = 0; j < 4; j++) {
                float p = expf(s_[i][j] - mn);
                s_[i][j] = p;
                rs += p;
            }
            rs += __shfl_xor_sync(0xffffffffu, rs, 8, 16);
            rs += __shfl_xor_sync(0xffffffffu, rs, 4, 16);
            rs += __shfl_xor_sync(0xffffffffu, rs, 2, 16);
            rs += __shfl_xor_sync(0xffffffffu, rs, 1, 16);
            l_[i] = l_[i] * alpha + rs;
            m_[i] = mn;
            #pragma unroll
            for (int j = 0; j < 4; j++) oacc[i][j] *= alpha;
            int qr = ty * 4 + i;
            #pragma unroll
            for (int j = 0; j < 4; j++) {
                int kc = tx * 4 + j;
                KP[qr][(kc + qr) & 63] = s_[i][j];
            }
        }
        __syncthreads();   // P ready

        // ---- O += P V ----
        #pragma unroll 4
        for (int kc = 0; kc < TK; kc++) {
            float rp[4], rv[4];
            #pragma unroll
            for (int i = 0; i < 4; i++) {
                int qr = ty * 4 + i;
                rp[i] = KP[qr][(kc + qr) & 63];
            }
            #pragma unroll
            for (int j = 0; j < 4; j++) rv[j] = Vs[kc][tx * 4 + j];
            #pragma unroll
            for (int i = 0; i < 4; i++)
                #pragma unroll
                for (int j = 0; j < 4; j++)
                    oacc[i][j] = fmaf(rp[i], rv[j], oacc[i][j]);
        }
        __syncthreads();   // done reading KP/Vs before next tile load
    }

    // ---- epilogue: normalize and write concat layout ----
    #pragma unroll
    for (int i = 0; i < 4; i++) {
        float inv = 1.f / l_[i];
        int q = q0 + ty * 4 + i;
        float4 o4;
        o4.x = oacc[i][0] * inv;
        o4.y = oacc[i][1] * inv;
        o4.z = oacc[i][2] * inv;
        o4.w = oacc[i][3] * inv;
        *(float4*)&g_C[((size_t)(b * NN) + q) * EE + h * DKK + tx * 4] = o4;
    }
}

// ---------------------------------------------------------------------------
// Kernel C0: transpose Wo so the projection GEMM reads coalesced.
// ---------------------------------------------------------------------------
__global__ void __launch_bounds__(256) wot_kernel(const float* __restrict__ Wo)
{
    int idx = blockIdx.x * 256 + threadIdx.x;   // [0, 65536)
    int o = idx >> 8, d = idx & 255;
    g_WoT[d * EE + o] = Wo[idx];
}

// ---------------------------------------------------------------------------
// Kernel C: out = concat @ Wo^T + bo. Same 8-row-tile structure as kernel A.
// ---------------------------------------------------------------------------
__global__ void __launch_bounds__(256) out_kernel(
    const float* __restrict__ bo, float* __restrict__ out)
{
    __shared__ float cs[8][EE];
    const int m0 = blockIdx.x * 8;
    const int t  = threadIdx.x;

    for (int i = t * 4; i < 8 * EE; i += 256 * 4) {
        int r = i >> 8, d = i & 255;
        *(float4*)&cs[r][d] = *(const float4*)&g_C[(size_t)(m0 + r) * EE + d];
    }
    __syncthreads();

    float acc[8] = {0.f, 0.f, 0.f, 0.f, 0.f, 0.f, 0.f, 0.f};
    #pragma unroll 2
    for (int d = 0; d < EE; d++) {
        float w = g_WoT[d * EE + t];
        #pragma unroll
        for (int r = 0; r < 8; r++) acc[r] = fmaf(cs[r][d], w, acc[r]);
    }
    float bv = bo[t];
    #pragma unroll
    for (int r = 0; r < 8; r++)
        out[(size_t)(m0 + r) * EE + t] = acc[r] + bv;
}

// ---------------------------------------------------------------------------
extern "C" void kernel_launch(void* const* d_in, const int* in_sizes, int n_in,
                              void* d_out, int out_size)
{
    const float* X   = (const float*)d_in[0];
    const int*   Adj = (const int*)  d_in[1];
    const float* Wq  = (const float*)d_in[2];
    const float* Wk  = (const float*)d_in[3];
    const float* Wv  = (const float*)d_in[4];
    const float* Wo  = (const float*)d_in[5];
    const float* bo  = (const float*)d_in[6];
    float* out = (float*)d_out;

    qkv_kernel<<<MTOT / 8, 256>>>(X, Wq, Wk, Wv);
    wot_kernel<<<EE * EE / 256, 256>>>(Wo);
    dim3 ag(NN / TQ, BB * HH);
    attn_kernel<<<ag, 256>>>(Adj);
    out_kernel<<<MTOT / 8, 256>>>(bo, out);
}